// round 16
// baseline (speedup 1.0000x reference)
#include <cuda_runtime.h>

#define TPB 256
#define MTPB 384
#define CTPB 480

// G=29 grid, D=15 disp, C=16 ch, S=48 spatial, NU=G*D=435, G3=24389, D3=3375

__device__ float g_f0t[110592 * 16];   // feat00 channel-last [z][y][x][c]
__device__ float g_f5t[110592 * 16];   // feat50 channel-last
__device__ float g_fix[24389 * 16];    // fixed samples [n][c]
__device__ float g_XI[16035840];       // X-interp [zy=2304][u=435][c=16]
__device__ float g_A[82312875];        // dc [n][m]
__device__ float g_B[82312875];        // scratch
__device__ float g_Cb[82312875];       // scratch

__device__ __forceinline__ float* bufsel(int id) {
    return id == 0 ? g_A : (id == 1 ? g_B : g_Cb);
}

__device__ __forceinline__ float4 lerp4(float4 a, float4 b, float w) {
    float4 r;
    r.x = a.x + w * (b.x - a.x);
    r.y = a.y + w * (b.y - a.y);
    r.z = a.z + w * (b.z - a.z);
    r.w = a.w + w * (b.w - a.w);
    return r;
}

__device__ __forceinline__ void pos_gs(int i, int j, int& k0, int& k1, float& w) {
    float c = (2.0f * i + 1.0f) / 29.0f - 1.0f;
    float s = 0.4f * ((2.0f * j + 1.0f) / 15.0f - 1.0f);
    float p = ((c + s + 1.0f) * 48.0f - 1.0f) * 0.5f;
    p = fminf(fmaxf(p, 0.0f), 47.0f);
    float f = floorf(p);
    k0 = (int)f;
    k1 = k0 + 1; if (k1 > 47) k1 = 47;
    w = p - f;
}

__device__ __forceinline__ void pos_g(int i, int& k0, int& k1, float& w) {
    float c = (2.0f * i + 1.0f) / 29.0f - 1.0f;
    float p = ((c + 1.0f) * 48.0f - 1.0f) * 0.5f;
    p = fminf(fmaxf(p, 0.0f), 47.0f);
    float f = floorf(p);
    k0 = (int)f;
    k1 = k0 + 1; if (k1 > 47) k1 = 47;
    w = p - f;
}

// ---------------------------------------------------------------------------
__global__ void __launch_bounds__(TPB) k_transpose(const float* __restrict__ f0,
                                                   const float* __restrict__ f5) {
    int t = blockIdx.x * TPB + threadIdx.x;
    if (t >= 110592 * 4) return;
    int q = t & 3;
    int v = t >> 2;
    int c0 = q * 4;
    float4 r0, r5;
    r0.x = f0[(c0 + 0) * 110592 + v];
    r0.y = f0[(c0 + 1) * 110592 + v];
    r0.z = f0[(c0 + 2) * 110592 + v];
    r0.w = f0[(c0 + 3) * 110592 + v];
    r5.x = f5[(c0 + 0) * 110592 + v];
    r5.y = f5[(c0 + 1) * 110592 + v];
    r5.z = f5[(c0 + 2) * 110592 + v];
    r5.w = f5[(c0 + 3) * 110592 + v];
    ((float4*)g_f0t)[v * 4 + q] = r0;
    ((float4*)g_f5t)[v * 4 + q] = r5;
}

__global__ void __launch_bounds__(TPB) k_fix() {
    int t = blockIdx.x * TPB + threadIdx.x;
    if (t >= 24389 * 4) return;
    int q = t & 3;
    int n = t >> 2;
    int ix = n % 29; int r = n / 29; int iy = r % 29; int iz = r / 29;
    int x0, x1, y0, y1, z0, z1; float wx, wy, wz;
    pos_g(ix, x0, x1, wx); pos_g(iy, y0, y1, wy); pos_g(iz, z0, z1, wz);
    const float4* F = (const float4*)g_f0t;
    float4 c00 = lerp4(F[((z0 * 48 + y0) * 48 + x0) * 4 + q], F[((z0 * 48 + y0) * 48 + x1) * 4 + q], wx);
    float4 c01 = lerp4(F[((z0 * 48 + y1) * 48 + x0) * 4 + q], F[((z0 * 48 + y1) * 48 + x1) * 4 + q], wx);
    float4 c10 = lerp4(F[((z1 * 48 + y0) * 48 + x0) * 4 + q], F[((z1 * 48 + y0) * 48 + x1) * 4 + q], wx);
    float4 c11 = lerp4(F[((z1 * 48 + y1) * 48 + x0) * 4 + q], F[((z1 * 48 + y1) * 48 + x1) * 4 + q], wx);
    float4 c0 = lerp4(c00, c01, wy);
    float4 c1 = lerp4(c10, c11, wy);
    ((float4*)g_fix)[n * 4 + q] = lerp4(c0, c1, wz);
}

__global__ void __launch_bounds__(TPB) k_stage1() {
    int t = blockIdx.x * TPB + threadIdx.x;
    if (t >= 4008960) return;                 // 2304 * 435 * 4
    int cq = t & 3;
    int r = t >> 2;
    int u = r % 435;
    int zy = r / 435;
    int ix = u / 15, jx = u % 15;
    int x0, x1; float wx;
    pos_gs(ix, jx, x0, x1, wx);
    const float4* F = (const float4*)g_f5t;
    float4 a = F[(zy * 48 + x0) * 4 + cq];
    float4 b = F[(zy * 48 + x1) * 4 + cq];
    ((float4*)g_XI)[(zy * 435 + u) * 4 + cq] = lerp4(a, b, wx);
}

// ---------------------------------------------------------------------------
// Fused z-lerp + y-lerp + channel cost reduction. Block = (ix, w).
// sZ cells padded to 20 floats (conflict-free LDS.128). Inner-loop index
// math hoisted into sY0/sWy tables (built once per block). 480 threads.
__global__ void __launch_bounds__(CTPB) k_cost(const float* __restrict__ alpha) {
    extern __shared__ float sZ[];             // 14400 floats (57600 B)
    int* sY0 = (int*)(sZ + 14400);            // 440
    float* sWy = sZ + 14840;                  // 440  (total 61120 B)
    int tid = threadIdx.x;
    int ixb = blockIdx.x;                     // 0..28
    int w = blockIdx.y;                       // 0..434
    int izg = w / 15, jz = w % 15;
    int z0, z1; float wz;
    pos_gs(izg, jz, z0, z1, wz);
    const float4* X = (const float4*)g_XI;
    for (int e = tid; e < 48 * 15 * 4; e += CTPB) {
        int q = e & 3; int r = e >> 2; int jxl = r % 15; int y = r / 15;
        int u = ixb * 15 + jxl;
        float4 a = X[((z0 * 48 + y) * 435 + u) * 4 + q];
        float4 b = X[((z1 * 48 + y) * 435 + u) * 4 + q];
        ((float4*)(sZ + (y * 15 + jxl) * 20))[q] = lerp4(a, b, wz);
    }
    for (int v = tid; v < 435; v += CTPB) {
        int iy = v / 15, jy = v % 15;
        int y0, y1; float wy;
        pos_gs(iy, jy, y0, y1, wy);
        sY0[v] = y0;
        sWy[v] = wy;
    }
    __syncthreads();

    int jx = tid % 15;
    int vlane = tid / 15;                     // 0..31
    float a0 = alpha[0], a1 = alpha[1];
    // 435 = 19*14 + 13*13
    int vs = vlane * 13 + min(vlane, 19);
    int ve = vs + 13 + (vlane < 19 ? 1 : 0);
    int iy = vs / 15, jy = vs % 15;
    int cur_iy = -1;
    float4 f0, f1, f2, f3;
    const float4* FX = (const float4*)g_fix;
    size_t obase = 0;
    for (int v = vs; v < ve; v++) {
        if (iy != cur_iy) {
            int nf = (izg * 29 + iy) * 29 + ixb;
            f0 = FX[nf * 4 + 0]; f1 = FX[nf * 4 + 1];
            f2 = FX[nf * 4 + 2]; f3 = FX[nf * 4 + 3];
            cur_iy = iy;
            obase = (size_t)nf * 3375 + (jz * 15) * 15 + jx;
        }
        int y0 = sY0[v];
        float wy = sWy[v];
        int y1 = y0 + 1 > 47 ? 47 : y0 + 1;
        const float4* r0 = (const float4*)(sZ + (y0 * 15 + jx) * 20);
        const float4* r1 = (const float4*)(sZ + (y1 * 15 + jx) * 20);
        float acc = 0.0f;
        {
            float4 a = r0[0], b = r1[0];
            float dx = f0.x - (a.x + wy * (b.x - a.x));
            float dy = f0.y - (a.y + wy * (b.y - a.y));
            float dz = f0.z - (a.z + wy * (b.z - a.z));
            float dw = f0.w - (a.w + wy * (b.w - a.w));
            acc += dx * dx + dy * dy + dz * dz + dw * dw;
        }
        {
            float4 a = r0[1], b = r1[1];
            float dx = f1.x - (a.x + wy * (b.x - a.x));
            float dy = f1.y - (a.y + wy * (b.y - a.y));
            float dz = f1.z - (a.z + wy * (b.z - a.z));
            float dw = f1.w - (a.w + wy * (b.w - a.w));
            acc += dx * dx + dy * dy + dz * dz + dw * dw;
        }
        {
            float4 a = r0[2], b = r1[2];
            float dx = f2.x - (a.x + wy * (b.x - a.x));
            float dy = f2.y - (a.y + wy * (b.y - a.y));
            float dz = f2.z - (a.z + wy * (b.z - a.z));
            float dw = f2.w - (a.w + wy * (b.w - a.w));
            acc += dx * dx + dy * dy + dz * dz + dw * dw;
        }
        {
            float4 a = r0[3], b = r1[3];
            float dx = f3.x - (a.x + wy * (b.x - a.x));
            float dy = f3.y - (a.y + wy * (b.y - a.y));
            float dz = f3.z - (a.z + wy * (b.z - a.z));
            float dw = f3.w - (a.w + wy * (b.w - a.w));
            acc += dx * dx + dy * dy + dz * dz + dw * dw;
        }
        g_A[obase + jy * 15] = a1 + a0 * acc;
        if (++jy == 15) { jy = 0; iy++; }
    }
}

// ---------------------------------------------------------------------------
// minavg chain. Input: per-thread registers x[15] (valid for tid<225).
__device__ __forceinline__ void minavg_chain(float* x, float* sA, float* sB,
                                             float* out, size_t base, int tid) {
    const float k0 = 1.0f / 9.0f, k1 = 2.0f / 9.0f, k2 = 3.0f / 9.0f;
    if (tid < 225) {
        float m[19];
#pragma unroll
        for (int u = 0; u < 19; u++) {
            int i0 = u - 3 < 0 ? 0 : (u - 3 > 14 ? 14 : u - 3);
            int i1 = u - 2 < 0 ? 0 : (u - 2 > 14 ? 14 : u - 2);
            int i2 = u - 1 < 0 ? 0 : (u - 1 > 14 ? 14 : u - 1);
            m[u] = fminf(x[i0], fminf(x[i1], x[i2]));
        }
        float4* ob = (float4*)(sB + tid * 20);
        ob[0] = make_float4(m[0], m[1], m[2], m[3]);
        ob[1] = make_float4(m[4], m[5], m[6], m[7]);
        ob[2] = make_float4(m[8], m[9], m[10], m[11]);
        ob[3] = make_float4(m[12], m[13], m[14], m[15]);
        sB[tid * 20 + 16] = m[16];
        sB[tid * 20 + 17] = m[17];
        sB[tid * 20 + 18] = m[18];
    }
    __syncthreads();
    if (tid < 285) {
        int z = tid / 19, u = tid - z * 19;
        float y[15];
        int b = z * 300 + u;
#pragma unroll
        for (int i = 0; i < 15; i++) y[i] = sB[b + i * 20];
        int ob = z * 361 + u;
#pragma unroll
        for (int v = 0; v < 19; v++) {
            int i0 = v - 3 < 0 ? 0 : (v - 3 > 14 ? 14 : v - 3);
            int i1 = v - 2 < 0 ? 0 : (v - 2 > 14 ? 14 : v - 2);
            int i2 = v - 1 < 0 ? 0 : (v - 1 > 14 ? 14 : v - 1);
            sA[ob + v * 19] = fminf(y[i0], fminf(y[i1], y[i2]));
        }
    }
    __syncthreads();
    if (tid < 361) {
        int v = tid / 19, u = tid - v * 19;
        float y[15];
#pragma unroll
        for (int i = 0; i < 15; i++) y[i] = sA[i * 361 + tid];
        int ob = v * 20 + u;
#pragma unroll
        for (int w = 0; w < 19; w++) {
            int i0 = w - 3 < 0 ? 0 : (w - 3 > 14 ? 14 : w - 3);
            int i1 = w - 2 < 0 ? 0 : (w - 2 > 14 ? 14 : w - 2);
            int i2 = w - 1 < 0 ? 0 : (w - 1 > 14 ? 14 : w - 1);
            sB[w * 380 + ob] = fminf(y[i0], fminf(y[i1], y[i2]));
        }
    }
    __syncthreads();
    if (tid < 361) {
        int w = tid / 19, v = tid - w * 19;
        const float4* ib = (const float4*)(sB + w * 380 + v * 20);
        float4 y0 = ib[0], y1 = ib[1], y2 = ib[2], y3 = ib[3];
        float y[19];
        y[0] = y0.x; y[1] = y0.y; y[2] = y0.z; y[3] = y0.w;
        y[4] = y1.x; y[5] = y1.y; y[6] = y1.z; y[7] = y1.w;
        y[8] = y2.x; y[9] = y2.y; y[10] = y2.z; y[11] = y2.w;
        y[12] = y3.x; y[13] = y3.y; y[14] = y3.z; y[15] = y3.w;
        y[16] = sB[w * 380 + v * 20 + 16];
        y[17] = sB[w * 380 + v * 20 + 17];
        y[18] = sB[w * 380 + v * 20 + 18];
        int ob = tid * 15;
#pragma unroll
        for (int t = 0; t < 15; t++)
            sA[ob + t] = k0 * (y[t] + y[t + 4]) + k1 * (y[t + 1] + y[t + 3]) + k2 * y[t + 2];
    }
    __syncthreads();
    if (tid < 285) {
        int w = tid / 15, t = tid - w * 15;
        float y[19];
        int b = w * 285 + t;
#pragma unroll
        for (int i = 0; i < 19; i++) y[i] = sA[b + i * 15];
        int ob = w * 225 + t;
#pragma unroll
        for (int ty = 0; ty < 15; ty++)
            sB[ob + ty * 15] = k0 * (y[ty] + y[ty + 4]) + k1 * (y[ty + 1] + y[ty + 3]) + k2 * y[ty + 2];
    }
    __syncthreads();
    if (tid < 225) {
        float y[19];
#pragma unroll
        for (int i = 0; i < 19; i++) y[i] = sB[i * 225 + tid];
#pragma unroll
        for (int tz = 0; tz < 15; tz++)
            out[base + tz * 225 + tid] =
                k0 * (y[tz] + y[tz + 4]) + k1 * (y[tz + 1] + y[tz + 3]) + k2 * y[tz + 2];
    }
}

#define SB_OFF 5416
#define CHAIN_SMEM ((SB_OFF + 7220) * 4)

__global__ void __launch_bounds__(MTPB) k_minavg(int inid, int outid) {
    extern __shared__ float sm[];
    float* sA = sm;
    float* sB = sm + SB_OFF;
    const float* in = bufsel(inid);
    int n = blockIdx.x;
    size_t base = (size_t)n * 3375;
    int tid = threadIdx.x;
    for (int o = tid; o < 3375; o += MTPB) sA[o] = in[base + o];
    __syncthreads();
    float x[15];
    if (tid < 225) {
#pragma unroll
        for (int i = 0; i < 15; i++) x[i] = sA[tid * 15 + i];
    }
    minavg_chain(x, sA, sB, bufsel(outid), base, tid);
}

// ---------------------------------------------------------------------------
__global__ void __launch_bounds__(448) k_gridxy(int inid, int outid) {
    extern __shared__ float s1[];             // [p=841][15] = 50460 B
    const float* in = bufsel(inid);
    float* outp = bufsel(outid);
    int iz = blockIdx.y;
    int m0 = blockIdx.x * 15;
    int tid = threadIdx.x;
    const float w0 = 1.0f / 9.0f, w1 = 2.0f / 9.0f, w2 = 3.0f / 9.0f;
    for (int e = tid; e < 12615; e += 448) {
        int p = e / 15, mm = e - p * 15;
        s1[e] = in[(size_t)(iz * 841 + p) * 3375 + m0 + mm];
    }
    __syncthreads();
    if (tid < 435) {
        int iy = tid / 15, mm = tid - iy * 15;
        int b = iy * 435 + mm;
        float x[29];
#pragma unroll
        for (int i = 0; i < 29; i++) x[i] = s1[b + i * 15];
#pragma unroll
        for (int i = 0; i < 29; i++) {
            int m2 = i - 2 < 0 ? 0 : i - 2, m1 = i - 1 < 0 ? 0 : i - 1;
            int p1 = i + 1 > 28 ? 28 : i + 1, p2 = i + 2 > 28 ? 28 : i + 2;
            s1[b + i * 15] = w0 * (x[m2] + x[p2]) + w1 * (x[m1] + x[p1]) + w2 * x[i];
        }
    }
    __syncthreads();
    if (tid < 435) {
        int ix = tid / 15, mm = tid - ix * 15;
        int b = ix * 15 + mm;
        float x[29];
#pragma unroll
        for (int i = 0; i < 29; i++) x[i] = s1[b + i * 435];
        size_t ob = (size_t)(iz * 841 + ix) * 3375 + m0 + mm;
#pragma unroll
        for (int i = 0; i < 29; i++) {
            int m2 = i - 2 < 0 ? 0 : i - 2, m1 = i - 1 < 0 ? 0 : i - 1;
            int p1 = i + 1 > 28 ? 28 : i + 1, p2 = i + 2 > 28 ? 28 : i + 2;
            outp[ob + (size_t)i * 29 * 3375] =
                w0 * (x[m2] + x[p2]) + w1 * (x[m1] + x[p1]) + w2 * x[i];
        }
    }
}

// ---------------------------------------------------------------------------
__global__ void __launch_bounds__(MTPB) k_gzcm(int cid, int dcid, int outid,
                                               const float* __restrict__ alpha) {
    extern __shared__ float sm[];
    float* sA = sm;
    float* sB = sm + SB_OFF;
    int n = blockIdx.x;
    int tid = threadIdx.x;
    int iz = n / 841;
    const float* Ci = bufsel(cid);
    const float* Dc = bufsel(dcid);
    size_t base = (size_t)n * 3375;
    float a2 = alpha[2], a3 = alpha[3], a4 = alpha[4];
    const float w0 = 1.0f / 9.0f, w1 = 2.0f / 9.0f, w2 = 3.0f / 9.0f;
    long long off[5];
#pragma unroll
    for (int d = 0; d < 5; d++) {
        int zd = iz + d - 2; if (zd < 0) zd = 0; if (zd > 28) zd = 28;
        off[d] = (long long)(zd - iz) * 841 * 3375;
    }
    for (int o = tid; o < 3375; o += MTPB) {
        float acc = w0 * (Ci[base + off[0] + o] + Ci[base + off[4] + o])
                  + w1 * (Ci[base + off[1] + o] + Ci[base + off[3] + o])
                  + w2 * Ci[base + off[2] + o];
        sA[o] = a4 + a2 * Dc[base + o] + a3 * acc;
    }
    __syncthreads();
    float x[15];
    if (tid < 225) {
#pragma unroll
        for (int j = 0; j < 15; j++) x[j] = sA[tid * 15 + j];
    }
    minavg_chain(x, sA, sB, bufsel(outid), base, tid);
}

// ---------------------------------------------------------------------------
__global__ void __launch_bounds__(TPB) k_gz_softmax(int inid, float* __restrict__ cost,
                                                    float* __restrict__ pred,
                                                    const float* __restrict__ alpha) {
    __shared__ float s[3375];
    __shared__ float redm[8];
    __shared__ float redv[8][4];
    int n = blockIdx.x;
    int tid = threadIdx.x;
    int iz = n / 841;
    const float* in = bufsel(inid);
    size_t base = (size_t)n * 3375;
    float a5 = alpha[5];
    const float w0 = 1.0f / 9.0f, w1 = 2.0f / 9.0f, w2 = 3.0f / 9.0f;
    long long off[5];
#pragma unroll
    for (int d = 0; d < 5; d++) {
        int zd = iz + d - 2; if (zd < 0) zd = 0; if (zd > 28) zd = 28;
        off[d] = (long long)(zd - iz) * 841 * 3375;
    }
    for (int m = tid; m < 3375; m += TPB) {
        float acc = w0 * (in[base + off[0] + m] + in[base + off[4] + m])
                  + w1 * (in[base + off[1] + m] + in[base + off[3] + m])
                  + w2 * in[base + off[2] + m];
        s[m] = -a5 * acc;
    }
    __syncthreads();

    float t[15];
    float lm = -3.4e38f;
    if (tid < 225) {
        int mb = tid * 15;
#pragma unroll
        for (int j = 0; j < 15; j++) {
            t[j] = s[mb + j];
            lm = fmaxf(lm, t[j]);
        }
    }
#pragma unroll
    for (int o2 = 16; o2; o2 >>= 1) lm = fmaxf(lm, __shfl_xor_sync(0xffffffffu, lm, o2));
    int wid = tid >> 5, lane = tid & 31;
    if (lane == 0) redm[wid] = lm;
    __syncthreads();
    if (tid == 0) {
        float M = redm[0];
        for (int i = 1; i < 8; i++) M = fmaxf(M, redm[i]);
        redm[0] = M;
    }
    __syncthreads();
    float M = redm[0];

    float ls = 0.0f, lx = 0.0f, ly = 0.0f, lz = 0.0f;
    if (tid < 225) {
        int jy = tid % 15, jz = tid / 15;
        float ty = 0.4f * ((2.0f * jy + 1.0f) * (1.0f / 15.0f) - 1.0f);
        float tz = 0.4f * ((2.0f * jz + 1.0f) * (1.0f / 15.0f) - 1.0f);
        int mb = tid * 15;
#pragma unroll
        for (int jx = 0; jx < 15; jx++) {
            float e = __expf(t[jx] - M);
            s[mb + jx] = e;
            ls += e;
            lx += e * (0.4f * ((2.0f * jx + 1.0f) * (1.0f / 15.0f) - 1.0f));
            ly += e * ty;
            lz += e * tz;
        }
    }
#pragma unroll
    for (int o2 = 16; o2; o2 >>= 1) {
        ls += __shfl_xor_sync(0xffffffffu, ls, o2);
        lx += __shfl_xor_sync(0xffffffffu, lx, o2);
        ly += __shfl_xor_sync(0xffffffffu, ly, o2);
        lz += __shfl_xor_sync(0xffffffffu, lz, o2);
    }
    if (lane == 0) { redv[wid][0] = ls; redv[wid][1] = lx; redv[wid][2] = ly; redv[wid][3] = lz; }
    __syncthreads();
    if (tid == 0) {
        float t0 = 0, t1 = 0, t2 = 0, t3 = 0;
        for (int i = 0; i < 8; i++) { t0 += redv[i][0]; t1 += redv[i][1]; t2 += redv[i][2]; t3 += redv[i][3]; }
        redv[0][0] = t0; redv[0][1] = t1; redv[0][2] = t2; redv[0][3] = t3;
    }
    __syncthreads();
    float inv = 1.0f / redv[0][0];
    if (cost) {
        for (int m = tid; m < 3375; m += TPB) cost[base + m] = s[m] * inv;
    }
    if (pred && tid == 0) {
        pred[n * 3 + 0] = redv[0][1] * inv;
        pred[n * 3 + 1] = redv[0][2] * inv;
        pred[n * 3 + 2] = redv[0][3] * inv;
    }
}

// ---------------------------------------------------------------------------
extern "C" void kernel_launch(void* const* d_in, const int* in_sizes, int n_in,
                              void* d_out, int out_size) {
    (void)in_sizes; (void)n_in;
    const float* feat00 = (const float*)d_in[0];
    const float* feat50 = (const float*)d_in[1];
    const float* alpha  = (const float*)d_in[2];
    float* outF = (float*)d_out;

    const long long CS = 82312875LL;
    const long long PR = 24389LL * 3;
    float* costPtr = nullptr;
    float* predPtr = nullptr;
    if ((long long)out_size >= CS) {
        costPtr = outF;
        if ((long long)out_size >= CS + PR) predPtr = outF + CS;
    } else if ((long long)out_size == PR) {
        predPtr = outF;
    }

    cudaFuncSetAttribute(k_cost, cudaFuncAttributeMaxDynamicSharedMemorySize, 61120);
    cudaFuncSetAttribute(k_gridxy, cudaFuncAttributeMaxDynamicSharedMemorySize, 50464);
    cudaFuncSetAttribute(k_minavg, cudaFuncAttributeMaxDynamicSharedMemorySize, CHAIN_SMEM);
    cudaFuncSetAttribute(k_gzcm, cudaFuncAttributeMaxDynamicSharedMemorySize, CHAIN_SMEM);

    k_transpose<<<(110592 * 4 + TPB - 1) / TPB, TPB>>>(feat00, feat50);
    k_fix<<<(24389 * 4 + TPB - 1) / TPB, TPB>>>();
    k_stage1<<<(4008960 + TPB - 1) / TPB, TPB>>>();

    // dc -> A
    k_cost<<<dim3(29, 435), CTPB, 61120>>>(alpha);

    // c1 = minavg_disp(dc): A -> B
    k_minavg<<<24389, MTPB, CHAIN_SMEM>>>(0, 1);

    // avg_grid xy: B -> C
    k_gridxy<<<dim3(225, 29), 448, 50460>>>(1, 2);

    // z-pass + combine with dc(A) + minavg: C,A -> B
    k_gzcm<<<24389, MTPB, CHAIN_SMEM>>>(2, 0, 1, alpha);

    // second avg_grid xy: B -> C
    k_gridxy<<<dim3(225, 29), 448, 50460>>>(1, 2);

    // z-pass + softmax + soft-argmax: C -> out
    k_gz_softmax<<<24389, TPB>>>(2, costPtr, predPtr, alpha);
}

// round 17
// speedup vs baseline: 1.0511x; 1.0511x over previous
#include <cuda_runtime.h>

#define TPB 256
#define MTPB 384
#define CTPB 448

// G=29 grid, D=15 disp, C=16 ch, S=48 spatial, NU=G*D=435, G3=24389, D3=3375

__device__ float g_f0t[110592 * 16];   // feat00 channel-last [z][y][x][c]
__device__ float g_f5t[110592 * 16];   // feat50 channel-last
__device__ float g_fix[24389 * 16];    // fixed samples [n][c]
__device__ float g_XI[16035840];       // X-interp [zy=2304][u=435][c=16]
__device__ float g_A[82312875];        // dc [n][m]
__device__ float g_B[82312875];        // scratch
__device__ float g_Cb[82312875];       // scratch

__device__ __forceinline__ float* bufsel(int id) {
    return id == 0 ? g_A : (id == 1 ? g_B : g_Cb);
}

__device__ __forceinline__ float4 lerp4(float4 a, float4 b, float w) {
    float4 r;
    r.x = a.x + w * (b.x - a.x);
    r.y = a.y + w * (b.y - a.y);
    r.z = a.z + w * (b.z - a.z);
    r.w = a.w + w * (b.w - a.w);
    return r;
}

__device__ __forceinline__ void pos_gs(int i, int j, int& k0, int& k1, float& w) {
    float c = (2.0f * i + 1.0f) / 29.0f - 1.0f;
    float s = 0.4f * ((2.0f * j + 1.0f) / 15.0f - 1.0f);
    float p = ((c + s + 1.0f) * 48.0f - 1.0f) * 0.5f;
    p = fminf(fmaxf(p, 0.0f), 47.0f);
    float f = floorf(p);
    k0 = (int)f;
    k1 = k0 + 1; if (k1 > 47) k1 = 47;
    w = p - f;
}

__device__ __forceinline__ void pos_g(int i, int& k0, int& k1, float& w) {
    float c = (2.0f * i + 1.0f) / 29.0f - 1.0f;
    float p = ((c + 1.0f) * 48.0f - 1.0f) * 0.5f;
    p = fminf(fmaxf(p, 0.0f), 47.0f);
    float f = floorf(p);
    k0 = (int)f;
    k1 = k0 + 1; if (k1 > 47) k1 = 47;
    w = p - f;
}

// ---------------------------------------------------------------------------
__global__ void __launch_bounds__(TPB) k_transpose(const float* __restrict__ f0,
                                                   const float* __restrict__ f5) {
    int t = blockIdx.x * TPB + threadIdx.x;
    if (t >= 110592 * 4) return;
    int q = t & 3;
    int v = t >> 2;
    int c0 = q * 4;
    float4 r0, r5;
    r0.x = f0[(c0 + 0) * 110592 + v];
    r0.y = f0[(c0 + 1) * 110592 + v];
    r0.z = f0[(c0 + 2) * 110592 + v];
    r0.w = f0[(c0 + 3) * 110592 + v];
    r5.x = f5[(c0 + 0) * 110592 + v];
    r5.y = f5[(c0 + 1) * 110592 + v];
    r5.z = f5[(c0 + 2) * 110592 + v];
    r5.w = f5[(c0 + 3) * 110592 + v];
    ((float4*)g_f0t)[v * 4 + q] = r0;
    ((float4*)g_f5t)[v * 4 + q] = r5;
}

__global__ void __launch_bounds__(TPB) k_fix() {
    int t = blockIdx.x * TPB + threadIdx.x;
    if (t >= 24389 * 4) return;
    int q = t & 3;
    int n = t >> 2;
    int ix = n % 29; int r = n / 29; int iy = r % 29; int iz = r / 29;
    int x0, x1, y0, y1, z0, z1; float wx, wy, wz;
    pos_g(ix, x0, x1, wx); pos_g(iy, y0, y1, wy); pos_g(iz, z0, z1, wz);
    const float4* F = (const float4*)g_f0t;
    float4 c00 = lerp4(F[((z0 * 48 + y0) * 48 + x0) * 4 + q], F[((z0 * 48 + y0) * 48 + x1) * 4 + q], wx);
    float4 c01 = lerp4(F[((z0 * 48 + y1) * 48 + x0) * 4 + q], F[((z0 * 48 + y1) * 48 + x1) * 4 + q], wx);
    float4 c10 = lerp4(F[((z1 * 48 + y0) * 48 + x0) * 4 + q], F[((z1 * 48 + y0) * 48 + x1) * 4 + q], wx);
    float4 c11 = lerp4(F[((z1 * 48 + y1) * 48 + x0) * 4 + q], F[((z1 * 48 + y1) * 48 + x1) * 4 + q], wx);
    float4 c0 = lerp4(c00, c01, wy);
    float4 c1 = lerp4(c10, c11, wy);
    ((float4*)g_fix)[n * 4 + q] = lerp4(c0, c1, wz);
}

__global__ void __launch_bounds__(TPB) k_stage1() {
    int t = blockIdx.x * TPB + threadIdx.x;
    if (t >= 4008960) return;                 // 2304 * 435 * 4
    int cq = t & 3;
    int r = t >> 2;
    int u = r % 435;
    int zy = r / 435;
    int ix = u / 15, jx = u % 15;
    int x0, x1; float wx;
    pos_gs(ix, jx, x0, x1, wx);
    const float4* F = (const float4*)g_f5t;
    float4 a = F[(zy * 48 + x0) * 4 + cq];
    float4 b = F[(zy * 48 + x1) * 4 + cq];
    ((float4*)g_XI)[(zy * 435 + u) * 4 + cq] = lerp4(a, b, wx);
}

// ---------------------------------------------------------------------------
// Fused z-lerp + y-lerp + channel cost reduction. Block = (ix, w).
// Thread = (iy, jx), jy inner loop with sliding 2-row register window:
// y0 advances monotonically, so when it advances by 1 the old y1 row is
// reused as the new y0 row (~33% fewer LDS bytes). Reuse branch is
// iy-group-uniform within a warp; predicated-off lanes cost no bank BW.
__global__ void __launch_bounds__(CTPB, 2) k_cost(const float* __restrict__ alpha) {
    extern __shared__ float sZ[];             // 14400 floats (57600 B)
    int* sY0 = (int*)(sZ + 14400);            // 440
    float* sWy = sZ + 14840;                  // 440  (total 61120 B)
    int tid = threadIdx.x;
    int ixb = blockIdx.x;                     // 0..28
    int w = blockIdx.y;                       // 0..434
    int izg = w / 15, jz = w % 15;
    int z0, z1; float wz;
    pos_gs(izg, jz, z0, z1, wz);
    const float4* X = (const float4*)g_XI;
    for (int e = tid; e < 48 * 15 * 4; e += CTPB) {
        int q = e & 3; int r = e >> 2; int jxl = r % 15; int y = r / 15;
        int u = ixb * 15 + jxl;
        float4 a = X[((z0 * 48 + y) * 435 + u) * 4 + q];
        float4 b = X[((z1 * 48 + y) * 435 + u) * 4 + q];
        ((float4*)(sZ + (y * 15 + jxl) * 20))[q] = lerp4(a, b, wz);
    }
    for (int v = tid; v < 435; v += CTPB) {
        int iy = v / 15, jy = v % 15;
        int y0, y1; float wy;
        pos_gs(iy, jy, y0, y1, wy);
        sY0[v] = y0;
        sWy[v] = wy;
    }
    __syncthreads();

    if (tid >= 435) return;
    int iy = tid / 15, jx = tid % 15;
    float a0 = alpha[0], a1 = alpha[1];
    int nf = (izg * 29 + iy) * 29 + ixb;
    const float4* FX = (const float4*)g_fix;
    float4 f0 = FX[nf * 4 + 0], f1 = FX[nf * 4 + 1];
    float4 f2 = FX[nf * 4 + 2], f3 = FX[nf * 4 + 3];
    size_t obase = (size_t)nf * 3375 + jz * 225 + jx;
    int tb = iy * 15;
    float4 R0a, R0b, R0c, R0d, R1a, R1b, R1c, R1d;
    R0a = R0b = R0c = R0d = R1a = R1b = R1c = R1d = make_float4(0.f, 0.f, 0.f, 0.f);
    int prevY0 = -9;
#pragma unroll
    for (int jy = 0; jy < 15; jy++) {
        int y0 = sY0[tb + jy];
        float wy = sWy[tb + jy];
        int y1 = y0 + 1 > 47 ? 47 : y0 + 1;
        if (y0 == prevY0 + 1) {
            // old y1 row (= prevY0+1 = y0) becomes new y0 row
            R0a = R1a; R0b = R1b; R0c = R1c; R0d = R1d;
        } else {
            const float4* p0 = (const float4*)(sZ + (y0 * 15 + jx) * 20);
            R0a = p0[0]; R0b = p0[1]; R0c = p0[2]; R0d = p0[3];
        }
        {
            const float4* p1 = (const float4*)(sZ + (y1 * 15 + jx) * 20);
            R1a = p1[0]; R1b = p1[1]; R1c = p1[2]; R1d = p1[3];
        }
        prevY0 = y0;
        float acc = 0.0f;
        {
            float dx = f0.x - (R0a.x + wy * (R1a.x - R0a.x));
            float dy = f0.y - (R0a.y + wy * (R1a.y - R0a.y));
            float dz = f0.z - (R0a.z + wy * (R1a.z - R0a.z));
            float dw = f0.w - (R0a.w + wy * (R1a.w - R0a.w));
            acc += dx * dx + dy * dy + dz * dz + dw * dw;
        }
        {
            float dx = f1.x - (R0b.x + wy * (R1b.x - R0b.x));
            float dy = f1.y - (R0b.y + wy * (R1b.y - R0b.y));
            float dz = f1.z - (R0b.z + wy * (R1b.z - R0b.z));
            float dw = f1.w - (R0b.w + wy * (R1b.w - R0b.w));
            acc += dx * dx + dy * dy + dz * dz + dw * dw;
        }
        {
            float dx = f2.x - (R0c.x + wy * (R1c.x - R0c.x));
            float dy = f2.y - (R0c.y + wy * (R1c.y - R0c.y));
            float dz = f2.z - (R0c.z + wy * (R1c.z - R0c.z));
            float dw = f2.w - (R0c.w + wy * (R1c.w - R0c.w));
            acc += dx * dx + dy * dy + dz * dz + dw * dw;
        }
        {
            float dx = f3.x - (R0d.x + wy * (R1d.x - R0d.x));
            float dy = f3.y - (R0d.y + wy * (R1d.y - R0d.y));
            float dz = f3.z - (R0d.z + wy * (R1d.z - R0d.z));
            float dw = f3.w - (R0d.w + wy * (R1d.w - R0d.w));
            acc += dx * dx + dy * dy + dz * dz + dw * dw;
        }
        g_A[obase + jy * 15] = a1 + a0 * acc;
    }
}

// ---------------------------------------------------------------------------
// minavg chain. Input: per-thread registers x[15] (valid for tid<225).
__device__ __forceinline__ void minavg_chain(float* x, float* sA, float* sB,
                                             float* out, size_t base, int tid) {
    const float k0 = 1.0f / 9.0f, k1 = 2.0f / 9.0f, k2 = 3.0f / 9.0f;
    if (tid < 225) {
        float m[19];
#pragma unroll
        for (int u = 0; u < 19; u++) {
            int i0 = u - 3 < 0 ? 0 : (u - 3 > 14 ? 14 : u - 3);
            int i1 = u - 2 < 0 ? 0 : (u - 2 > 14 ? 14 : u - 2);
            int i2 = u - 1 < 0 ? 0 : (u - 1 > 14 ? 14 : u - 1);
            m[u] = fminf(x[i0], fminf(x[i1], x[i2]));
        }
        float4* ob = (float4*)(sB + tid * 20);
        ob[0] = make_float4(m[0], m[1], m[2], m[3]);
        ob[1] = make_float4(m[4], m[5], m[6], m[7]);
        ob[2] = make_float4(m[8], m[9], m[10], m[11]);
        ob[3] = make_float4(m[12], m[13], m[14], m[15]);
        sB[tid * 20 + 16] = m[16];
        sB[tid * 20 + 17] = m[17];
        sB[tid * 20 + 18] = m[18];
    }
    __syncthreads();
    if (tid < 285) {
        int z = tid / 19, u = tid - z * 19;
        float y[15];
        int b = z * 300 + u;
#pragma unroll
        for (int i = 0; i < 15; i++) y[i] = sB[b + i * 20];
        int ob = z * 361 + u;
#pragma unroll
        for (int v = 0; v < 19; v++) {
            int i0 = v - 3 < 0 ? 0 : (v - 3 > 14 ? 14 : v - 3);
            int i1 = v - 2 < 0 ? 0 : (v - 2 > 14 ? 14 : v - 2);
            int i2 = v - 1 < 0 ? 0 : (v - 1 > 14 ? 14 : v - 1);
            sA[ob + v * 19] = fminf(y[i0], fminf(y[i1], y[i2]));
        }
    }
    __syncthreads();
    if (tid < 361) {
        int v = tid / 19, u = tid - v * 19;
        float y[15];
#pragma unroll
        for (int i = 0; i < 15; i++) y[i] = sA[i * 361 + tid];
        int ob = v * 20 + u;
#pragma unroll
        for (int w = 0; w < 19; w++) {
            int i0 = w - 3 < 0 ? 0 : (w - 3 > 14 ? 14 : w - 3);
            int i1 = w - 2 < 0 ? 0 : (w - 2 > 14 ? 14 : w - 2);
            int i2 = w - 1 < 0 ? 0 : (w - 1 > 14 ? 14 : w - 1);
            sB[w * 380 + ob] = fminf(y[i0], fminf(y[i1], y[i2]));
        }
    }
    __syncthreads();
    if (tid < 361) {
        int w = tid / 19, v = tid - w * 19;
        const float4* ib = (const float4*)(sB + w * 380 + v * 20);
        float4 y0 = ib[0], y1 = ib[1], y2 = ib[2], y3 = ib[3];
        float y[19];
        y[0] = y0.x; y[1] = y0.y; y[2] = y0.z; y[3] = y0.w;
        y[4] = y1.x; y[5] = y1.y; y[6] = y1.z; y[7] = y1.w;
        y[8] = y2.x; y[9] = y2.y; y[10] = y2.z; y[11] = y2.w;
        y[12] = y3.x; y[13] = y3.y; y[14] = y3.z; y[15] = y3.w;
        y[16] = sB[w * 380 + v * 20 + 16];
        y[17] = sB[w * 380 + v * 20 + 17];
        y[18] = sB[w * 380 + v * 20 + 18];
        int ob = tid * 15;
#pragma unroll
        for (int t = 0; t < 15; t++)
            sA[ob + t] = k0 * (y[t] + y[t + 4]) + k1 * (y[t + 1] + y[t + 3]) + k2 * y[t + 2];
    }
    __syncthreads();
    if (tid < 285) {
        int w = tid / 15, t = tid - w * 15;
        float y[19];
        int b = w * 285 + t;
#pragma unroll
        for (int i = 0; i < 19; i++) y[i] = sA[b + i * 15];
        int ob = w * 225 + t;
#pragma unroll
        for (int ty = 0; ty < 15; ty++)
            sB[ob + ty * 15] = k0 * (y[ty] + y[ty + 4]) + k1 * (y[ty + 1] + y[ty + 3]) + k2 * y[ty + 2];
    }
    __syncthreads();
    if (tid < 225) {
        float y[19];
#pragma unroll
        for (int i = 0; i < 19; i++) y[i] = sB[i * 225 + tid];
#pragma unroll
        for (int tz = 0; tz < 15; tz++)
            out[base + tz * 225 + tid] =
                k0 * (y[tz] + y[tz + 4]) + k1 * (y[tz + 1] + y[tz + 3]) + k2 * y[tz + 2];
    }
}

#define SB_OFF 5416
#define CHAIN_SMEM ((SB_OFF + 7220) * 4)

__global__ void __launch_bounds__(MTPB) k_minavg(int inid, int outid) {
    extern __shared__ float sm[];
    float* sA = sm;
    float* sB = sm + SB_OFF;
    const float* in = bufsel(inid);
    int n = blockIdx.x;
    size_t base = (size_t)n * 3375;
    int tid = threadIdx.x;
    for (int o = tid; o < 3375; o += MTPB) sA[o] = in[base + o];
    __syncthreads();
    float x[15];
    if (tid < 225) {
#pragma unroll
        for (int i = 0; i < 15; i++) x[i] = sA[tid * 15 + i];
    }
    minavg_chain(x, sA, sB, bufsel(outid), base, tid);
}

// ---------------------------------------------------------------------------
__global__ void __launch_bounds__(448) k_gridxy(int inid, int outid) {
    extern __shared__ float s1[];             // [p=841][15] = 50460 B
    const float* in = bufsel(inid);
    float* outp = bufsel(outid);
    int iz = blockIdx.y;
    int m0 = blockIdx.x * 15;
    int tid = threadIdx.x;
    const float w0 = 1.0f / 9.0f, w1 = 2.0f / 9.0f, w2 = 3.0f / 9.0f;
    for (int e = tid; e < 12615; e += 448) {
        int p = e / 15, mm = e - p * 15;
        s1[e] = in[(size_t)(iz * 841 + p) * 3375 + m0 + mm];
    }
    __syncthreads();
    if (tid < 435) {
        int iy = tid / 15, mm = tid - iy * 15;
        int b = iy * 435 + mm;
        float x[29];
#pragma unroll
        for (int i = 0; i < 29; i++) x[i] = s1[b + i * 15];
#pragma unroll
        for (int i = 0; i < 29; i++) {
            int m2 = i - 2 < 0 ? 0 : i - 2, m1 = i - 1 < 0 ? 0 : i - 1;
            int p1 = i + 1 > 28 ? 28 : i + 1, p2 = i + 2 > 28 ? 28 : i + 2;
            s1[b + i * 15] = w0 * (x[m2] + x[p2]) + w1 * (x[m1] + x[p1]) + w2 * x[i];
        }
    }
    __syncthreads();
    if (tid < 435) {
        int ix = tid / 15, mm = tid - ix * 15;
        int b = ix * 15 + mm;
        float x[29];
#pragma unroll
        for (int i = 0; i < 29; i++) x[i] = s1[b + i * 435];
        size_t ob = (size_t)(iz * 841 + ix) * 3375 + m0 + mm;
#pragma unroll
        for (int i = 0; i < 29; i++) {
            int m2 = i - 2 < 0 ? 0 : i - 2, m1 = i - 1 < 0 ? 0 : i - 1;
            int p1 = i + 1 > 28 ? 28 : i + 1, p2 = i + 2 > 28 ? 28 : i + 2;
            outp[ob + (size_t)i * 29 * 3375] =
                w0 * (x[m2] + x[p2]) + w1 * (x[m1] + x[p1]) + w2 * x[i];
        }
    }
}

// ---------------------------------------------------------------------------
__global__ void __launch_bounds__(MTPB) k_gzcm(int cid, int dcid, int outid,
                                               const float* __restrict__ alpha) {
    extern __shared__ float sm[];
    float* sA = sm;
    float* sB = sm + SB_OFF;
    int n = blockIdx.x;
    int tid = threadIdx.x;
    int iz = n / 841;
    const float* Ci = bufsel(cid);
    const float* Dc = bufsel(dcid);
    size_t base = (size_t)n * 3375;
    float a2 = alpha[2], a3 = alpha[3], a4 = alpha[4];
    const float w0 = 1.0f / 9.0f, w1 = 2.0f / 9.0f, w2 = 3.0f / 9.0f;
    long long off[5];
#pragma unroll
    for (int d = 0; d < 5; d++) {
        int zd = iz + d - 2; if (zd < 0) zd = 0; if (zd > 28) zd = 28;
        off[d] = (long long)(zd - iz) * 841 * 3375;
    }
    for (int o = tid; o < 3375; o += MTPB) {
        float acc = w0 * (Ci[base + off[0] + o] + Ci[base + off[4] + o])
                  + w1 * (Ci[base + off[1] + o] + Ci[base + off[3] + o])
                  + w2 * Ci[base + off[2] + o];
        sA[o] = a4 + a2 * Dc[base + o] + a3 * acc;
    }
    __syncthreads();
    float x[15];
    if (tid < 225) {
#pragma unroll
        for (int j = 0; j < 15; j++) x[j] = sA[tid * 15 + j];
    }
    minavg_chain(x, sA, sB, bufsel(outid), base, tid);
}

// ---------------------------------------------------------------------------
__global__ void __launch_bounds__(TPB) k_gz_softmax(int inid, float* __restrict__ cost,
                                                    float* __restrict__ pred,
                                                    const float* __restrict__ alpha) {
    __shared__ float s[3375];
    __shared__ float redm[8];
    __shared__ float redv[8][4];
    int n = blockIdx.x;
    int tid = threadIdx.x;
    int iz = n / 841;
    const float* in = bufsel(inid);
    size_t base = (size_t)n * 3375;
    float a5 = alpha[5];
    const float w0 = 1.0f / 9.0f, w1 = 2.0f / 9.0f, w2 = 3.0f / 9.0f;
    long long off[5];
#pragma unroll
    for (int d = 0; d < 5; d++) {
        int zd = iz + d - 2; if (zd < 0) zd = 0; if (zd > 28) zd = 28;
        off[d] = (long long)(zd - iz) * 841 * 3375;
    }
    for (int m = tid; m < 3375; m += TPB) {
        float acc = w0 * (in[base + off[0] + m] + in[base + off[4] + m])
                  + w1 * (in[base + off[1] + m] + in[base + off[3] + m])
                  + w2 * in[base + off[2] + m];
        s[m] = -a5 * acc;
    }
    __syncthreads();

    float t[15];
    float lm = -3.4e38f;
    if (tid < 225) {
        int mb = tid * 15;
#pragma unroll
        for (int j = 0; j < 15; j++) {
            t[j] = s[mb + j];
            lm = fmaxf(lm, t[j]);
        }
    }
#pragma unroll
    for (int o2 = 16; o2; o2 >>= 1) lm = fmaxf(lm, __shfl_xor_sync(0xffffffffu, lm, o2));
    int wid = tid >> 5, lane = tid & 31;
    if (lane == 0) redm[wid] = lm;
    __syncthreads();
    if (tid == 0) {
        float M = redm[0];
        for (int i = 1; i < 8; i++) M = fmaxf(M, redm[i]);
        redm[0] = M;
    }
    __syncthreads();
    float M = redm[0];

    float ls = 0.0f, lx = 0.0f, ly = 0.0f, lz = 0.0f;
    if (tid < 225) {
        int jy = tid % 15, jz = tid / 15;
        float ty = 0.4f * ((2.0f * jy + 1.0f) * (1.0f / 15.0f) - 1.0f);
        float tz = 0.4f * ((2.0f * jz + 1.0f) * (1.0f / 15.0f) - 1.0f);
        int mb = tid * 15;
#pragma unroll
        for (int jx = 0; jx < 15; jx++) {
            float e = __expf(t[jx] - M);
            s[mb + jx] = e;
            ls += e;
            lx += e * (0.4f * ((2.0f * jx + 1.0f) * (1.0f / 15.0f) - 1.0f));
            ly += e * ty;
            lz += e * tz;
        }
    }
#pragma unroll
    for (int o2 = 16; o2; o2 >>= 1) {
        ls += __shfl_xor_sync(0xffffffffu, ls, o2);
        lx += __shfl_xor_sync(0xffffffffu, lx, o2);
        ly += __shfl_xor_sync(0xffffffffu, ly, o2);
        lz += __shfl_xor_sync(0xffffffffu, lz, o2);
    }
    if (lane == 0) { redv[wid][0] = ls; redv[wid][1] = lx; redv[wid][2] = ly; redv[wid][3] = lz; }
    __syncthreads();
    if (tid == 0) {
        float t0 = 0, t1 = 0, t2 = 0, t3 = 0;
        for (int i = 0; i < 8; i++) { t0 += redv[i][0]; t1 += redv[i][1]; t2 += redv[i][2]; t3 += redv[i][3]; }
        redv[0][0] = t0; redv[0][1] = t1; redv[0][2] = t2; redv[0][3] = t3;
    }
    __syncthreads();
    float inv = 1.0f / redv[0][0];
    if (cost) {
        for (int m = tid; m < 3375; m += TPB) cost[base + m] = s[m] * inv;
    }
    if (pred && tid == 0) {
        pred[n * 3 + 0] = redv[0][1] * inv;
        pred[n * 3 + 1] = redv[0][2] * inv;
        pred[n * 3 + 2] = redv[0][3] * inv;
    }
}

// ---------------------------------------------------------------------------
extern "C" void kernel_launch(void* const* d_in, const int* in_sizes, int n_in,
                              void* d_out, int out_size) {
    (void)in_sizes; (void)n_in;
    const float* feat00 = (const float*)d_in[0];
    const float* feat50 = (const float*)d_in[1];
    const float* alpha  = (const float*)d_in[2];
    float* outF = (float*)d_out;

    const long long CS = 82312875LL;
    const long long PR = 24389LL * 3;
    float* costPtr = nullptr;
    float* predPtr = nullptr;
    if ((long long)out_size >= CS) {
        costPtr = outF;
        if ((long long)out_size >= CS + PR) predPtr = outF + CS;
    } else if ((long long)out_size == PR) {
        predPtr = outF;
    }

    cudaFuncSetAttribute(k_cost, cudaFuncAttributeMaxDynamicSharedMemorySize, 61120);
    cudaFuncSetAttribute(k_gridxy, cudaFuncAttributeMaxDynamicSharedMemorySize, 50464);
    cudaFuncSetAttribute(k_minavg, cudaFuncAttributeMaxDynamicSharedMemorySize, CHAIN_SMEM);
    cudaFuncSetAttribute(k_gzcm, cudaFuncAttributeMaxDynamicSharedMemorySize, CHAIN_SMEM);

    k_transpose<<<(110592 * 4 + TPB - 1) / TPB, TPB>>>(feat00, feat50);
    k_fix<<<(24389 * 4 + TPB - 1) / TPB, TPB>>>();
    k_stage1<<<(4008960 + TPB - 1) / TPB, TPB>>>();

    // dc -> A
    k_cost<<<dim3(29, 435), CTPB, 61120>>>(alpha);

    // c1 = minavg_disp(dc): A -> B
    k_minavg<<<24389, MTPB, CHAIN_SMEM>>>(0, 1);

    // avg_grid xy: B -> C
    k_gridxy<<<dim3(225, 29), 448, 50460>>>(1, 2);

    // z-pass + combine with dc(A) + minavg: C,A -> B
    k_gzcm<<<24389, MTPB, CHAIN_SMEM>>>(2, 0, 1, alpha);

    // second avg_grid xy: B -> C
    k_gridxy<<<dim3(225, 29), 448, 50460>>>(1, 2);

    // z-pass + softmax + soft-argmax: C -> out
    k_gz_softmax<<<24389, TPB>>>(2, costPtr, predPtr, alpha);
}